// round 9
// baseline (speedup 1.0000x reference)
#include <cuda_runtime.h>

// SymmetricChannel: out[b,l,:] = one_hot(replacement_symbol) if (rand_u < P && argmax(msg)!=0)
//                                else message[b,l,:]
// B=64, L=4096, V=128, P=0.1
//
// Persistent single-wave grid (SMs x 8 CTAs), one warp streams ~27 rows via a
// 2-deep software pipeline: next row's loads issue before current row's
// reduction+store -> load latency hidden, no wave transitions, no front-batch
// L1tex burst. Warp argmax: REDUX.MAX on float bits (uniform [0,1) inputs ->
// positive floats, bit order == value order) + ballot + 1 shfl; lowest
// matching lane preserves jnp.argmax first-index tiebreak.

#define NROWS (64 * 4096)
#define VOCAB 128

__device__ __forceinline__ float4 ldg_v4_pinned(const float4* p) {
    float4 v;
    asm volatile("ld.global.nc.v4.f32 {%0,%1,%2,%3}, [%4];"
                 : "=f"(v.x), "=f"(v.y), "=f"(v.z), "=f"(v.w)
                 : "l"(p));
    return v;
}

__global__ __launch_bounds__(256, 8) void sym_channel_kernel(
    const float* __restrict__ message,
    const float* __restrict__ rand_u,
    const int*   __restrict__ repl_idx,
    float*       __restrict__ out)
{
    const int warps_total = gridDim.x * (blockDim.x >> 5);
    const int gwarp = blockIdx.x * (blockDim.x >> 5) + (threadIdx.x >> 5);
    const int lane = threadIdx.x & 31;
    const int base = lane * 4;

    const float4* __restrict__ min4 = reinterpret_cast<const float4*>(message);
    float4*       __restrict__ out4 = reinterpret_cast<float4*>(out);

    int row = gwarp;
    if (row >= NROWS) return;

    // ---- prologue: load row 0 of this warp's stream ----
    float4 v  = ldg_v4_pinned(min4 + (size_t)row * (VOCAB / 4) + lane);
    float  ru = __ldg(rand_u + row);
    int    ri = __ldg(repl_idx + row);

    while (true) {
        // ---- prefetch next row BEFORE touching current row's data ----
        const int next = row + warps_total;          // warp-uniform
        const bool have_next = next < NROWS;
        float4 vn; float run = 0.f; int rin = 0;
        if (have_next) {
            vn  = ldg_v4_pinned(min4 + (size_t)next * (VOCAB / 4) + lane);
            run = __ldg(rand_u + next);
            rin = __ldg(repl_idx + next);
        }

        // ---- process current row ----
        float best = v.x; int bidx = base;
        if (v.y > best) { best = v.y; bidx = base + 1; }
        if (v.z > best) { best = v.z; bidx = base + 2; }
        if (v.w > best) { best = v.w; bidx = base + 3; }

        const unsigned bb   = __float_as_uint(best);
        const unsigned wm   = __reduce_max_sync(0xffffffffu, bb);
        const unsigned ball = __ballot_sync(0xffffffffu, bb == wm);
        const int amax = __shfl_sync(0xffffffffu, bidx, __ffs(ball) - 1);

        const bool combined = (ru < 0.1f) && (amax != 0);
        // msg != 0 when combined, so msg_exp == amax.
        const int r1 = ri + 1;
        const int rs = r1 + (r1 >= amax ? 1 : 0);    // in [1, V-1], != amax
        float4 o;
        o.x = combined ? ((rs == base    ) ? 1.0f : 0.0f) : v.x;
        o.y = combined ? ((rs == base + 1) ? 1.0f : 0.0f) : v.y;
        o.z = combined ? ((rs == base + 2) ? 1.0f : 0.0f) : v.z;
        o.w = combined ? ((rs == base + 3) ? 1.0f : 0.0f) : v.w;
        out4[(size_t)row * (VOCAB / 4) + lane] = o;

        if (!have_next) break;
        v = vn; ru = run; ri = rin; row = next;
    }
}

extern "C" void kernel_launch(void* const* d_in, const int* in_sizes, int n_in,
                              void* d_out, int out_size)
{
    const float* message  = (const float*)d_in[0];
    const float* rand_u   = (const float*)d_in[1];
    const int*   repl_idx = (const int*)  d_in[2];
    float*       out      = (float*)d_out;

    // One full wave: SM count x 8 CTAs of 256 threads (regs <= 32 -> 8 fit).
    int sms = 0;
    if (cudaDeviceGetAttribute(&sms, cudaDevAttrMultiProcessorCount, 0) != cudaSuccess || sms <= 0)
        sms = 148;
    const int blocks = sms * 8;
    sym_channel_kernel<<<blocks, 256>>>(message, rand_u, repl_idx, out);
}

// round 11
// speedup vs baseline: 1.0557x; 1.0557x over previous
#include <cuda_runtime.h>

// SymmetricChannel: out[b,l,:] = one_hot(replacement_symbol) if (rand_u < P && argmax(msg)!=0)
//                                else message[b,l,:]
// B=64, L=4096, V=128, P=0.1
//
// Best-measured shape (2 rows/warp, 8 warps/block) + pinned asm loads
// (guaranteed MLP=2 in SASS) + warp-uniform skip: when neither row of the
// pair is a corruption target (~81% of pairs), both REDUX argmax chains are
// skipped entirely. The branch sits AFTER the loads issue, so memory
// pipelining is unaffected (lesson from R7).

#define NROWS (64 * 4096)
#define VOCAB 128

__device__ __forceinline__ float4 ldg_v4_pinned(const float4* p) {
    float4 v;
    asm volatile("ld.global.nc.v4.f32 {%0,%1,%2,%3}, [%4];"
                 : "=f"(v.x), "=f"(v.y), "=f"(v.z), "=f"(v.w)
                 : "l"(p));
    return v;
}

__global__ __launch_bounds__(256) void sym_channel_kernel(
    const float* __restrict__ message,
    const float* __restrict__ rand_u,
    const int*   __restrict__ repl_idx,
    float*       __restrict__ out)
{
    const int warp = blockIdx.x * (blockDim.x >> 5) + (threadIdx.x >> 5);
    const int lane = threadIdx.x & 31;
    const int row0 = warp * 2;
    if (row0 >= NROWS) return;
    const int base = lane * 4;

    const float4* __restrict__ min4 = reinterpret_cast<const float4*>(message);
    float4*       __restrict__ out4 = reinterpret_cast<float4*>(out);

    // ---- all loads issued back-to-back, pinned (MLP = 2 big + 1 scalar) ----
    const size_t off0 = (size_t)row0 * (VOCAB / 4) + lane;
    float4 v0 = ldg_v4_pinned(min4 + off0);
    float4 v1 = ldg_v4_pinned(min4 + off0 + (VOCAB / 4));
    const float2 ruv = *reinterpret_cast<const float2*>(rand_u + row0);  // broadcast

    // Warp-uniform fast path: neither row is a corruption target (~81%).
    // Loads are already in flight; this only removes the reduction chains.
    if (ruv.x >= 0.1f && ruv.y >= 0.1f) {
        out4[off0]               = v0;
        out4[off0 + (VOCAB / 4)] = v1;
        return;
    }

    // ---- slow path: at least one row needs the argmax ----
    const int2 riv = *reinterpret_cast<const int2*>(repl_idx + row0);

    // Local argmax, both rows (independent chains), first-index tiebreak.
    float b0 = v0.x; int i0 = base;
    if (v0.y > b0) { b0 = v0.y; i0 = base + 1; }
    if (v0.z > b0) { b0 = v0.z; i0 = base + 2; }
    if (v0.w > b0) { b0 = v0.w; i0 = base + 3; }
    float b1 = v1.x; int i1 = base;
    if (v1.y > b1) { b1 = v1.y; i1 = base + 1; }
    if (v1.z > b1) { b1 = v1.z; i1 = base + 2; }
    if (v1.w > b1) { b1 = v1.w; i1 = base + 3; }

    // Batched warp argmax: REDUX on bits (uniform [0,1) -> positive floats,
    // bit order == value order); lowest matching lane = first index.
    const unsigned bb0 = __float_as_uint(b0), bb1 = __float_as_uint(b1);
    const unsigned wm0 = __reduce_max_sync(0xffffffffu, bb0);
    const unsigned wm1 = __reduce_max_sync(0xffffffffu, bb1);
    const unsigned ba0 = __ballot_sync(0xffffffffu, bb0 == wm0);
    const unsigned ba1 = __ballot_sync(0xffffffffu, bb1 == wm1);
    const int amax0 = __shfl_sync(0xffffffffu, i0, __ffs(ba0) - 1);
    const int amax1 = __shfl_sync(0xffffffffu, i1, __ffs(ba1) - 1);

    // Branchless select + store.
    {
        const bool c = (ruv.x < 0.1f) && (amax0 != 0);
        const int r1 = riv.x + 1;
        const int rs = r1 + (r1 >= amax0 ? 1 : 0);   // in [1, V-1], != amax0
        float4 o;
        o.x = c ? ((rs == base    ) ? 1.0f : 0.0f) : v0.x;
        o.y = c ? ((rs == base + 1) ? 1.0f : 0.0f) : v0.y;
        o.z = c ? ((rs == base + 2) ? 1.0f : 0.0f) : v0.z;
        o.w = c ? ((rs == base + 3) ? 1.0f : 0.0f) : v0.w;
        out4[off0] = o;
    }
    {
        const bool c = (ruv.y < 0.1f) && (amax1 != 0);
        const int r1 = riv.y + 1;
        const int rs = r1 + (r1 >= amax1 ? 1 : 0);
        float4 o;
        o.x = c ? ((rs == base    ) ? 1.0f : 0.0f) : v1.x;
        o.y = c ? ((rs == base + 1) ? 1.0f : 0.0f) : v1.y;
        o.z = c ? ((rs == base + 2) ? 1.0f : 0.0f) : v1.z;
        o.w = c ? ((rs == base + 3) ? 1.0f : 0.0f) : v1.w;
        out4[off0 + (VOCAB / 4)] = o;
    }
}

extern "C" void kernel_launch(void* const* d_in, const int* in_sizes, int n_in,
                              void* d_out, int out_size)
{
    const float* message  = (const float*)d_in[0];
    const float* rand_u   = (const float*)d_in[1];
    const int*   repl_idx = (const int*)  d_in[2];
    float*       out      = (float*)d_out;

    const int warps_per_block = 8;
    const int rows_per_block  = warps_per_block * 2;                   // 16
    const int blocks = (NROWS + rows_per_block - 1) / rows_per_block;  // 16384
    sym_channel_kernel<<<blocks, warps_per_block * 32>>>(message, rand_u, repl_idx, out);
}

// round 12
// speedup vs baseline: 1.0588x; 1.0029x over previous
#include <cuda_runtime.h>

// SymmetricChannel: out[b,l,:] = one_hot(replacement_symbol) if (rand_u < P && argmax(msg)!=0)
//                                else message[b,l,:]
// B=64, L=4096, V=128, P=0.1
//
// Merges the two measured wins:
//  - R8: 4 rows/warp with asm-pinned back-to-back ld.global.v4 (SASS-guaranteed
//    MLP=4; ptxas cannot sink volatile asm loads).
//  - R11: warp-uniform skip AFTER loads issue — 0.9^4 ~ 66% of warps take a
//    pure load->store path with no reduction chains at all.
// Slow path batches all four REDUX argmax chains so their latencies overlap.
// Warp argmax: REDUX.MAX on float bits (uniform [0,1) inputs -> positive
// floats, bit order == value order) + ballot + 1 shfl; lowest matching lane
// preserves jnp.argmax first-index tiebreak.

#define NROWS (64 * 4096)
#define VOCAB 128
#define RPW 4

__device__ __forceinline__ float4 ldg_v4_pinned(const float4* p) {
    float4 v;
    asm volatile("ld.global.nc.v4.f32 {%0,%1,%2,%3}, [%4];"
                 : "=f"(v.x), "=f"(v.y), "=f"(v.z), "=f"(v.w)
                 : "l"(p));
    return v;
}

__global__ __launch_bounds__(256) void sym_channel_kernel(
    const float* __restrict__ message,
    const float* __restrict__ rand_u,
    const int*   __restrict__ repl_idx,
    float*       __restrict__ out)
{
    const int warp = blockIdx.x * (blockDim.x >> 5) + (threadIdx.x >> 5);
    const int lane = threadIdx.x & 31;
    const int row0 = warp * RPW;
    if (row0 >= NROWS) return;
    const int base = lane * 4;

    const float4* __restrict__ min4 = reinterpret_cast<const float4*>(message);
    float4*       __restrict__ out4 = reinterpret_cast<float4*>(out);

    // ---- all loads issued back-to-back, pinned (MLP = 4 big + 1 scalar) ----
    const size_t off0 = (size_t)row0 * (VOCAB / 4) + lane;
    float4 v0 = ldg_v4_pinned(min4 + off0);
    float4 v1 = ldg_v4_pinned(min4 + off0 + (VOCAB / 4));
    float4 v2 = ldg_v4_pinned(min4 + off0 + 2 * (VOCAB / 4));
    float4 v3 = ldg_v4_pinned(min4 + off0 + 3 * (VOCAB / 4));
    const float4 ruv = *reinterpret_cast<const float4*>(rand_u + row0);  // broadcast

    // Warp-uniform fast path (~66%): no row is a corruption target.
    // Loads already in flight; this only removes the reduction chains.
    if (ruv.x >= 0.1f && ruv.y >= 0.1f && ruv.z >= 0.1f && ruv.w >= 0.1f) {
        out4[off0]                   = v0;
        out4[off0 +     (VOCAB / 4)] = v1;
        out4[off0 + 2 * (VOCAB / 4)] = v2;
        out4[off0 + 3 * (VOCAB / 4)] = v3;
        return;
    }

    // ---- slow path: at least one row needs the argmax ----
    const int4 riv = *reinterpret_cast<const int4*>(repl_idx + row0);
    float4 v[RPW] = { v0, v1, v2, v3 };
    const float ru[RPW] = { ruv.x, ruv.y, ruv.z, ruv.w };
    const int   ri[RPW] = { riv.x, riv.y, riv.z, riv.w };

    // Local argmax, independent chains, first-index tiebreak (strict >).
    float best[RPW]; int bidx[RPW];
    #pragma unroll
    for (int r = 0; r < RPW; r++) {
        best[r] = v[r].x; bidx[r] = base;
        if (v[r].y > best[r]) { best[r] = v[r].y; bidx[r] = base + 1; }
        if (v[r].z > best[r]) { best[r] = v[r].z; bidx[r] = base + 2; }
        if (v[r].w > best[r]) { best[r] = v[r].w; bidx[r] = base + 3; }
    }

    // Batched warp argmax so the REDUX/BALLOT/SHFL latencies overlap.
    unsigned bb[RPW], wm[RPW], ba[RPW]; int amax[RPW];
    #pragma unroll
    for (int r = 0; r < RPW; r++) bb[r] = __float_as_uint(best[r]);
    #pragma unroll
    for (int r = 0; r < RPW; r++) wm[r] = __reduce_max_sync(0xffffffffu, bb[r]);
    #pragma unroll
    for (int r = 0; r < RPW; r++) ba[r] = __ballot_sync(0xffffffffu, bb[r] == wm[r]);
    #pragma unroll
    for (int r = 0; r < RPW; r++)
        amax[r] = __shfl_sync(0xffffffffu, bidx[r], __ffs(ba[r]) - 1);

    // Branchless select + store.
    #pragma unroll
    for (int r = 0; r < RPW; r++) {
        const bool c = (ru[r] < 0.1f) && (amax[r] != 0);
        // msg != 0 when c, so msg_exp == amax.
        const int r1 = ri[r] + 1;
        const int rs = r1 + (r1 >= amax[r] ? 1 : 0);   // in [1, V-1], != amax
        float4 o;
        o.x = c ? ((rs == base    ) ? 1.0f : 0.0f) : v[r].x;
        o.y = c ? ((rs == base + 1) ? 1.0f : 0.0f) : v[r].y;
        o.z = c ? ((rs == base + 2) ? 1.0f : 0.0f) : v[r].z;
        o.w = c ? ((rs == base + 3) ? 1.0f : 0.0f) : v[r].w;
        out4[off0 + r * (VOCAB / 4)] = o;
    }
}

extern "C" void kernel_launch(void* const* d_in, const int* in_sizes, int n_in,
                              void* d_out, int out_size)
{
    const float* message  = (const float*)d_in[0];
    const float* rand_u   = (const float*)d_in[1];
    const int*   repl_idx = (const int*)  d_in[2];
    float*       out      = (float*)d_out;

    const int warps_per_block = 8;
    const int rows_per_block  = warps_per_block * RPW;                 // 32
    const int blocks = (NROWS + rows_per_block - 1) / rows_per_block;  // 8192
    sym_channel_kernel<<<blocks, warps_per_block * 32>>>(message, rand_u, repl_idx, out);
}